// round 7
// baseline (speedup 1.0000x reference)
#include <cuda_runtime.h>
#include <math.h>

#define DIM 192
#define NB 12
#define PZ 16
#define BLKV 4096
#define THREADS 256

// accumulators: [0]=sum(p*g) [1]=sum(p*p) [2]=sum(g*g) [3]=loss_cl
__device__ double g_acc[4];

__global__ void init_acc_kernel() {
    if (threadIdx.x < 4) g_acc[threadIdx.x] = 0.0;
}

__device__ __forceinline__ float warp_sum(float v) {
#pragma unroll
    for (int o = 16; o; o >>= 1) v += __shfl_xor_sync(0xffffffffu, v, o);
    return v;
}

// ---------- stencil passes: thread owns column (x,y), 16 z-voxels ----------

// 7-point cross min, +inf padding == skip out-of-range
__device__ void pass_erode(const float* __restrict__ in, float* __restrict__ out,
                           int t, int x, int y) {
#pragma unroll
    for (int k = 0; k < 16; k++) {
        int v = (k << 8) + t;
        float m = in[v];
        if (k > 0)   m = fminf(m, in[v - 256]);
        if (k < 15)  m = fminf(m, in[v + 256]);
        if (x > 0)   m = fminf(m, in[v - 16]);
        if (x < 15)  m = fminf(m, in[v + 16]);
        if (y > 0)   m = fminf(m, in[v - 1]);
        if (y < 15)  m = fminf(m, in[v + 1]);
        out[v] = m;
    }
}

// 27-point box max, -inf padding == skip out-of-range
__device__ void pass_dilate(const float* __restrict__ in, float* __restrict__ out,
                            int t, int x, int y) {
    int xlo = (x > 0) ? -1 : 0, xhi = (x < 15) ? 1 : 0;
    int ylo = (y > 0) ? -1 : 0, yhi = (y < 15) ? 1 : 0;
#pragma unroll 2
    for (int k = 0; k < 16; k++) {
        int v = (k << 8) + t;
        int zlo = (k > 0) ? -1 : 0, zhi = (k < 15) ? 1 : 0;
        float m = in[v];
        for (int dz = zlo; dz <= zhi; dz++)
            for (int dx = xlo; dx <= xhi; dx++)
                for (int dy = ylo; dy <= yhi; dy++)
                    m = fmaxf(m, in[v + dz * 256 + dx * 16 + dy]);
        out[v] = m;
    }
}

__device__ void pass_skel_init(const float* __restrict__ img, const float* __restrict__ dil,
                               float* __restrict__ skel, int t) {
#pragma unroll
    for (int k = 0; k < 16; k++) {
        int v = (k << 8) + t;
        skel[v] = fmaxf(img[v] - dil[v], 0.0f);
    }
}

__device__ void pass_skel_update(const float* __restrict__ ecur, const float* __restrict__ dil,
                                 float* __restrict__ skel, int t) {
#pragma unroll
    for (int k = 0; k < 16; k++) {
        int v = (k << 8) + t;
        float delta = fmaxf(ecur[v] - dil[v], 0.0f);
        float s = skel[v];
        skel[v] = s + fmaxf(delta - s * delta, 0.0f);
    }
}

// soft_skel, ITERS=3: e1..e4, deltas vs dilate(e_{k+1}); img destroyed; result in skel.
__device__ void soft_skel_seq(float* img, float* w0, float* w1, float* skel,
                              int t, int x, int y) {
    pass_erode(img, w0, t, x, y);          __syncthreads();
    pass_dilate(w0, w1, t, x, y);          __syncthreads();
    pass_skel_init(img, w1, skel, t);      __syncthreads();
    pass_erode(w0, img, t, x, y);          __syncthreads();
    pass_dilate(img, w1, t, x, y);         __syncthreads();
    pass_skel_update(w0, w1, skel, t);     __syncthreads();
    pass_erode(img, w0, t, x, y);          __syncthreads();
    pass_dilate(w0, w1, t, x, y);          __syncthreads();
    pass_skel_update(img, w1, skel, t);    __syncthreads();
    pass_erode(w0, img, t, x, y);          __syncthreads();
    pass_dilate(img, w1, t, x, y);         __syncthreads();
    pass_skel_update(w0, w1, skel, t);     __syncthreads();
}

__device__ __forceinline__ double block_tversky(double tp, double fn, double fp) {
    const double s = 1e-8;
    double ab = fp + fn + s;
    double alpha = 0.5 + 0.5 * (fp + s) / ab;
    double beta  = 0.5 + 0.5 * (fn + s) / ab;
    return 1.0 - (tp + s) / (tp + alpha * fp + beta * fn + s);
}

extern __shared__ float smem[];

__global__ void __launch_bounds__(THREADS, 2)
loss_main_kernel(const float* __restrict__ pred, const float* __restrict__ gt) {
    float* b0 = smem;              // gt (destroyed) -> pred skel
    float* b1 = smem + BLKV;       // pred (destroyed)
    float* b2 = smem + 2 * BLKV;   // scratch w0
    float* b3 = smem + 3 * BLKV;   // gt skel
    float* b4 = smem + 4 * BLKV;   // scratch w1

    int t = threadIdx.x;
    int b = blockIdx.x;
    int by = b % NB;
    int bx = (b / NB) % NB;
    int bz = (b / (NB * NB)) % NB;
    int n  = b / (NB * NB * NB);

    long base = (long)n * DIM * DIM * DIM
              + (long)(bz * PZ) * DIM * DIM
              + (long)(bx * PZ) * DIM
              + (long)(by * PZ);

    int x = t >> 4;
    int y = t & 15;

    // ---- load + dice partials ----
    float pg = 0.f, pp = 0.f, gg = 0.f;
#pragma unroll
    for (int k = 0; k < 16; k++) {
        long gi = base + (long)k * DIM * DIM + x * DIM + y;
        float g = gt[gi];
        float p = pred[gi];
        int v = (k << 8) + t;
        b0[v] = g;
        b1[v] = p;
        pg += p * g;
        pp += p * p;
        gg += g * g;
    }
    __syncthreads();

    // NOTE: the reference's laplacian-boundary kernel is
    //   -(ones.at[13].set(26))  => all -1 with center -26  (unary minus binds last!)
    // so b = -(26c + sum_neighbors) <= 0 for nonneg inputs, (b > 0.1) is always
    // false, all boundary maps are zero, and loss_bdr == 0 identically.
    // The boundary term is therefore dropped entirely.

    // ---- skeletons ----
    soft_skel_seq(b0, b2, b4, b3, t, x, y);   // gt  skel -> b3
    soft_skel_seq(b1, b2, b4, b0, t, x, y);   // pred skel -> b0

    // ---- clDice tversky counts ----
    float tpc = 0.f, fnc = 0.f, fpc = 0.f;
#pragma unroll
    for (int k = 0; k < 16; k++) {
        int v = (k << 8) + t;
        float sg = b3[v];   // gt skel
        float sp = b0[v];   // pred skel
        tpc += sg * sp;
        fnc += sg * (1.0f - sp);
        fpc += (1.0f - sg) * sp;
    }

    // ---- block reduction ----
    __shared__ float red[8][6];
    float vals[6] = {pg, pp, gg, tpc, fnc, fpc};
    int lane = t & 31, w = t >> 5;
#pragma unroll
    for (int i = 0; i < 6; i++) {
        float s = warp_sum(vals[i]);
        if (lane == 0) red[w][i] = s;
    }
    __syncthreads();

    if (t == 0) {
        double s[6];
#pragma unroll
        for (int i = 0; i < 6; i++) {
            double acc = 0.0;
#pragma unroll
            for (int ww = 0; ww < 8; ww++) acc += (double)red[ww][i];
            s[i] = acc;
        }
        atomicAdd(&g_acc[0], s[0]);
        atomicAdd(&g_acc[1], s[1]);
        atomicAdd(&g_acc[2], s[2]);
        atomicAdd(&g_acc[3], block_tversky(s[3], s[4], s[5]));
    }
}

__global__ void final_kernel(const float* __restrict__ w1,
                             const float* __restrict__ w2,
                             float* __restrict__ out, int M) {
    double pg = g_acc[0], pp = g_acc[1], gg = g_acc[2];
    double dice = 2.0 * pg / fmax(pp + gg, 1e-6);
    double dice_loss = 1.0 - dice;
    double w1s = (double)w1[0], w2s = (double)w2[0];
    // loss_bdr == 0 identically (see note in main kernel)
    double edge = (g_acc[3] / (w2s * w2s)) / (2.0 * (double)M)
                + log(1.0 + fabs(w1s) * fabs(w2s));
    out[0] = (float)((dice < 0.8) ? dice_loss : dice_loss + edge);
}

extern "C" void kernel_launch(void* const* d_in, const int* in_sizes, int n_in,
                              void* d_out, int out_size) {
    const float* pred = (const float*)d_in[0];
    const float* gt   = (const float*)d_in[1];
    const float* w1   = (const float*)d_in[2];
    const float* w2   = (const float*)d_in[3];
    float* out = (float*)d_out;

    int total = in_sizes[0];
    int N = total / (DIM * DIM * DIM);
    int nblk = N * NB * NB * NB;

    cudaFuncSetAttribute(loss_main_kernel,
                         cudaFuncAttributeMaxDynamicSharedMemorySize,
                         5 * BLKV * (int)sizeof(float));

    init_acc_kernel<<<1, 32>>>();
    loss_main_kernel<<<nblk, THREADS, 5 * BLKV * sizeof(float)>>>(pred, gt);
    final_kernel<<<1, 1>>>(w1, w2, out, nblk);
}

// round 8
// speedup vs baseline: 5.2723x; 5.2723x over previous
#include <cuda_runtime.h>
#include <math.h>

#define DIM 192
#define NB 12
#define BLKV 4096
#define THREADS 256

// accumulators: [0]=sum(p*g) [1]=sum(p*p) [2]=sum(g*g) [3]=loss_cl
__device__ double g_acc[4];

__global__ void init_acc_kernel() {
    if (threadIdx.x < 4) g_acc[threadIdx.x] = 0.0;
}

__device__ __forceinline__ float warp_sum(float v) {
#pragma unroll
    for (int o = 16; o; o >>= 1) v += __shfl_xor_sync(0xffffffffu, v, o);
    return v;
}

// ---------------------------------------------------------------------------
// Register-resident column model: thread (x,y) owns 16 z-voxels in registers.
// smem buffers are used only to exchange x/y neighbor columns.
// Publish/consume buffers strictly alternate A,B,A,B,... across ALL stages:
// a thread writes buffer X only after passing the sync that followed the last
// stage that read X, so one __syncthreads per publish is sufficient.
// ---------------------------------------------------------------------------

// erode: publish v, sync, e = min(v, z±1(reg), x±1, y±1)   (+inf padding)
__device__ __forceinline__ void erode_reg(float* __restrict__ wbuf,
                                          const float (&v)[16], float (&e)[16],
                                          int t, int x, int y) {
#pragma unroll
    for (int k = 0; k < 16; k++) wbuf[(k << 8) + t] = v[k];
    __syncthreads();
#pragma unroll
    for (int k = 0; k < 16; k++) {
        float m = v[k];
        if (k > 0)   m = fminf(m, v[k - 1]);
        if (k < 15)  m = fminf(m, v[k + 1]);
        if (x > 0)   m = fminf(m, wbuf[(k << 8) + t - 16]);
        if (x < 15)  m = fminf(m, wbuf[(k << 8) + t + 16]);
        if (y > 0)   m = fminf(m, wbuf[(k << 8) + t - 1]);
        if (y < 15)  m = fminf(m, wbuf[(k << 8) + t + 1]);
        e[k] = m;
    }
}

// separable 3x3x3 dilate: max_z in regs -> publish(b1) -> max_x -> publish(b2) -> max_y
// (-inf padding == skip out-of-range)
__device__ __forceinline__ void dilate_reg(float* __restrict__ b1,
                                           float* __restrict__ b2,
                                           const float (&e)[16], float (&d)[16],
                                           int t, int x, int y) {
    float mz[16];
#pragma unroll
    for (int k = 0; k < 16; k++) {
        float m = e[k];
        if (k > 0)   m = fmaxf(m, e[k - 1]);
        if (k < 15)  m = fmaxf(m, e[k + 1]);
        mz[k] = m;
        b1[(k << 8) + t] = m;
    }
    __syncthreads();
    float mx[16];
#pragma unroll
    for (int k = 0; k < 16; k++) {
        float m = mz[k];
        if (x > 0)   m = fmaxf(m, b1[(k << 8) + t - 16]);
        if (x < 15)  m = fmaxf(m, b1[(k << 8) + t + 16]);
        mx[k] = m;
        b2[(k << 8) + t] = m;
    }
    __syncthreads();
#pragma unroll
    for (int k = 0; k < 16; k++) {
        float m = mx[k];
        if (y > 0)   m = fmaxf(m, b2[(k << 8) + t - 1]);
        if (y < 15)  m = fmaxf(m, b2[(k << 8) + t + 1]);
        d[k] = m;
    }
}

// soft_skel (ITERS=3), all elementwise state in registers.
// Publish order: A,B,A | B,A,B | A,B,A | B,A,B  -- strict alternation.
__device__ __forceinline__ void soft_skel_reg(float* __restrict__ bA,
                                              float* __restrict__ bB,
                                              const float (&img)[16],
                                              float (&skel)[16],
                                              int t, int x, int y) {
    float e1[16], e2[16], d[16];

    erode_reg(bA, img, e1, t, x, y);          // pub A
    dilate_reg(bB, bA, e1, d, t, x, y);       // pub B, A
#pragma unroll
    for (int k = 0; k < 16; k++)
        skel[k] = fmaxf(img[k] - d[k], 0.0f);

    // iter 1: e2 = erode(e1); delta vs dilate(e2)
    erode_reg(bB, e1, e2, t, x, y);           // pub B
    dilate_reg(bA, bB, e2, d, t, x, y);       // pub A, B
#pragma unroll
    for (int k = 0; k < 16; k++) {
        float delta = fmaxf(e1[k] - d[k], 0.0f);
        skel[k] += fmaxf(delta - skel[k] * delta, 0.0f);
    }

    // iter 2: e1 = erode(e2)
    erode_reg(bA, e2, e1, t, x, y);           // pub A
    dilate_reg(bB, bA, e1, d, t, x, y);       // pub B, A
#pragma unroll
    for (int k = 0; k < 16; k++) {
        float delta = fmaxf(e2[k] - d[k], 0.0f);
        skel[k] += fmaxf(delta - skel[k] * delta, 0.0f);
    }

    // iter 3: e2 = erode(e1)
    erode_reg(bB, e1, e2, t, x, y);           // pub B
    dilate_reg(bA, bB, e2, d, t, x, y);       // pub A, B
#pragma unroll
    for (int k = 0; k < 16; k++) {
        float delta = fmaxf(e1[k] - d[k], 0.0f);
        skel[k] += fmaxf(delta - skel[k] * delta, 0.0f);
    }
}

__device__ __forceinline__ double block_tversky(double tp, double fn, double fp) {
    const double s = 1e-8;
    double ab = fp + fn + s;
    double alpha = 0.5 + 0.5 * (fp + s) / ab;
    double beta  = 0.5 + 0.5 * (fn + s) / ab;
    return 1.0 - (tp + s) / (tp + alpha * fp + beta * fn + s);
}

extern __shared__ float smem[];

__global__ void __launch_bounds__(THREADS, 2)
loss_main_kernel(const float* __restrict__ pred, const float* __restrict__ gt) {
    float* bA = smem;              // exchange buffer A
    float* bB = smem + BLKV;       // exchange buffer B
    float* bC = smem + 2 * BLKV;   // pred parking

    int t = threadIdx.x;
    int b = blockIdx.x;
    int by = b % NB;
    int bx = (b / NB) % NB;
    int bz = (b / (NB * NB)) % NB;
    int n  = b / (NB * NB * NB);

    long base = (long)n * DIM * DIM * DIM
              + (long)(bz * 16) * DIM * DIM
              + (long)(bx * 16) * DIM
              + (long)(by * 16);

    int x = t >> 4;
    int y = t & 15;

    // ---- load into registers + dice partials; park pred in bC ----
    float g[16], p[16];
    float pg = 0.f, pp = 0.f, gg = 0.f;
#pragma unroll
    for (int k = 0; k < 16; k++) {
        long gi = base + (long)k * DIM * DIM + x * DIM + y;
        float gv = gt[gi];
        float pv = pred[gi];
        g[k] = gv;
        p[k] = pv;
        bC[(k << 8) + t] = pv;
        pg += pv * gv;
        pp += pv * pv;
        gg += gv * gv;
    }

    // NOTE: the reference's boundary conv kernel is -(ones.at[13].set(26))
    // => all taps negative => (b > 0.1) is identically false => loss_bdr == 0.
    // Boundary term dropped.

    float skel_g[16], skel_p[16];
    soft_skel_reg(bA, bB, g, skel_g, t, x, y);      // ends having published ...B

    // reload pred (own column, self-written)
#pragma unroll
    for (int k = 0; k < 16; k++) p[k] = bC[(k << 8) + t];

    soft_skel_reg(bA, bB, p, skel_p, t, x, y);      // starts publishing A: alternation holds

    // ---- clDice tversky counts (registers only) ----
    float tpc = 0.f, fnc = 0.f, fpc = 0.f;
#pragma unroll
    for (int k = 0; k < 16; k++) {
        float sg = skel_g[k];
        float sp = skel_p[k];
        tpc += sg * sp;
        fnc += sg * (1.0f - sp);
        fpc += (1.0f - sg) * sp;
    }

    // ---- block reduction ----
    __shared__ float red[8][6];
    float vals[6] = {pg, pp, gg, tpc, fnc, fpc};
    int lane = t & 31, w = t >> 5;
#pragma unroll
    for (int i = 0; i < 6; i++) {
        float s = warp_sum(vals[i]);
        if (lane == 0) red[w][i] = s;
    }
    __syncthreads();

    if (t == 0) {
        double s[6];
#pragma unroll
        for (int i = 0; i < 6; i++) {
            double acc = 0.0;
#pragma unroll
            for (int ww = 0; ww < 8; ww++) acc += (double)red[ww][i];
            s[i] = acc;
        }
        atomicAdd(&g_acc[0], s[0]);
        atomicAdd(&g_acc[1], s[1]);
        atomicAdd(&g_acc[2], s[2]);
        atomicAdd(&g_acc[3], block_tversky(s[3], s[4], s[5]));
    }
}

__global__ void final_kernel(const float* __restrict__ w1,
                             const float* __restrict__ w2,
                             float* __restrict__ out, int M) {
    double pg = g_acc[0], pp = g_acc[1], gg = g_acc[2];
    double dice = 2.0 * pg / fmax(pp + gg, 1e-6);
    double dice_loss = 1.0 - dice;
    double w1s = (double)w1[0], w2s = (double)w2[0];
    double edge = (g_acc[3] / (w2s * w2s)) / (2.0 * (double)M)
                + log(1.0 + fabs(w1s) * fabs(w2s));
    out[0] = (float)((dice < 0.8) ? dice_loss : dice_loss + edge);
}

extern "C" void kernel_launch(void* const* d_in, const int* in_sizes, int n_in,
                              void* d_out, int out_size) {
    const float* pred = (const float*)d_in[0];
    const float* gt   = (const float*)d_in[1];
    const float* w1   = (const float*)d_in[2];
    const float* w2   = (const float*)d_in[3];
    float* out = (float*)d_out;

    int total = in_sizes[0];
    int N = total / (DIM * DIM * DIM);
    int nblk = N * NB * NB * NB;

    cudaFuncSetAttribute(loss_main_kernel,
                         cudaFuncAttributeMaxDynamicSharedMemorySize,
                         3 * BLKV * (int)sizeof(float));

    init_acc_kernel<<<1, 32>>>();
    loss_main_kernel<<<nblk, THREADS, 3 * BLKV * sizeof(float)>>>(pred, gt);
    final_kernel<<<1, 1>>>(w1, w2, out, nblk);
}

// round 9
// speedup vs baseline: 10.8432x; 2.0566x over previous
#include <cuda_runtime.h>
#include <math.h>

#define DIM 192
#define NB 12
#define BLKV 4096
#define THREADS 256
#define FULLM 0xffffffffu

// accumulators: [0]=sum(p*g) [1]=sum(p*p) [2]=sum(g*g) [3]=loss_cl
__device__ double g_acc[4];

__global__ void init_acc_kernel() {
    if (threadIdx.x < 4) g_acc[threadIdx.x] = 0.0;
}

__device__ __forceinline__ float warp_sum(float v) {
#pragma unroll
    for (int o = 16; o; o >>= 1) v += __shfl_xor_sync(FULLM, v, o);
    return v;
}

// ---------------------------------------------------------------------------
// Thread (x,y) owns 16 z-voxels in registers.  lane = (x&1)*16 + y, so:
//   y+-1  : lane+-1  (shfl up/down, pad handled by guards)
//   x^1   : lane^16  (shfl_xor; always in-range: even x -> x+1<=15, odd -> x-1>=0)
//   other x-tap: smem, 1 guarded LDS/voxel (publish own column first)
// One publish + one __syncthreads per stage; buffers A/B strictly alternate.
// ---------------------------------------------------------------------------

// erode: e = min over z+-1 (regs), x+-1 (shfl + smem), y+-1 (shfl); +inf pad
__device__ __forceinline__ void erode_stage(float* __restrict__ buf,
                                            const float (&v)[16], float (&e)[16],
                                            int t, int to, bool xv, int y) {
#pragma unroll
    for (int k = 0; k < 16; k++) buf[(k << 8) + t] = v[k];
    __syncthreads();
#pragma unroll
    for (int k = 0; k < 16; k++) {
        float m = v[k];
        if (k > 0)   m = fminf(m, v[k - 1]);
        if (k < 15)  m = fminf(m, v[k + 1]);
        m = fminf(m, __shfl_xor_sync(FULLM, v[k], 16));      // x^1 neighbor
        float o = buf[(k << 8) + to];                         // other x neighbor
        if (xv) m = fminf(m, o);
        float yu = __shfl_up_sync(FULLM, v[k], 1);
        if (y > 0)  m = fminf(m, yu);
        float yd = __shfl_down_sync(FULLM, v[k], 1);
        if (y < 15) m = fminf(m, yd);
        e[k] = m;
    }
}

// dilate 3x3x3 (separable, -inf pad) fused with skel init/update.
// z-max in regs -> publish -> sync -> x-max (shfl + smem) -> y-max (shfl) -> update.
template <bool FIRST>
__device__ __forceinline__ void dilate_update_stage(float* __restrict__ buf,
                                                    const float (&e)[16],
                                                    const float (&prev)[16],
                                                    float (&skel)[16],
                                                    int t, int to, bool xv, int y) {
#pragma unroll
    for (int k = 0; k < 16; k++) {
        float m = e[k];
        if (k > 0)   m = fmaxf(m, e[k - 1]);
        if (k < 15)  m = fmaxf(m, e[k + 1]);
        buf[(k << 8) + t] = m;            // publish z-max; reloaded below (saves regs)
    }
    __syncthreads();
#pragma unroll
    for (int k = 0; k < 16; k++) {
        float m = buf[(k << 8) + t];                          // own z-max
        m = fmaxf(m, __shfl_xor_sync(FULLM, m, 16));          // x^1
        float o = buf[(k << 8) + to];                         // other x
        if (xv) m = fmaxf(m, o);
        // y-pass on the completed x-max via shuffles (no publish, no sync)
        float yu = __shfl_up_sync(FULLM, m, 1);
        float yd = __shfl_down_sync(FULLM, m, 1);
        float d = m;
        if (y > 0)  d = fmaxf(d, yu);
        if (y < 15) d = fmaxf(d, yd);
        float delta = fmaxf(prev[k] - d, 0.0f);
        if (FIRST) {
            skel[k] = delta;
        } else {
            float s = skel[k];
            skel[k] = s + fmaxf(delta - s * delta, 0.0f);
        }
    }
}

// soft_skel ITERS=3.  img destroyed (reused as scratch).  Stages alternate A,B.
__device__ __forceinline__ void soft_skel_reg(float* __restrict__ bA,
                                              float* __restrict__ bB,
                                              float (&img)[16], float (&skel)[16],
                                              int t, int to, bool xv, int y) {
    float e1[16];
    erode_stage(bA, img, e1, t, to, xv, y);                       // e1 = erode(img)
    dilate_update_stage<true>(bB, e1, img, skel, t, to, xv, y);   // skel = relu(img - dil(e1))

    erode_stage(bA, e1, img, t, to, xv, y);                       // img <- e2
    dilate_update_stage<false>(bB, img, e1, skel, t, to, xv, y);  // delta vs e1

    erode_stage(bA, img, e1, t, to, xv, y);                       // e1 <- e3
    dilate_update_stage<false>(bB, e1, img, skel, t, to, xv, y);  // delta vs e2

    erode_stage(bA, e1, img, t, to, xv, y);                       // img <- e4
    dilate_update_stage<false>(bB, img, e1, skel, t, to, xv, y);  // delta vs e3
}

__device__ __forceinline__ double block_tversky(double tp, double fn, double fp) {
    const double s = 1e-8;
    double ab = fp + fn + s;
    double alpha = 0.5 + 0.5 * (fp + s) / ab;
    double beta  = 0.5 + 0.5 * (fn + s) / ab;
    return 1.0 - (tp + s) / (tp + alpha * fp + beta * fn + s);
}

extern __shared__ float smem[];

__global__ void __launch_bounds__(THREADS, 3)
loss_main_kernel(const float* __restrict__ pred, const float* __restrict__ gt) {
    float* bA = smem;              // exchange buffer A (erode publishes)
    float* bB = smem + BLKV;       // exchange buffer B (dilate publishes)
    float* bC = smem + 2 * BLKV;   // pred parking

    int t = threadIdx.x;
    int b = blockIdx.x;
    int by = b % NB;
    int bx = (b / NB) % NB;
    int bz = (b / (NB * NB)) % NB;
    int n  = b / (NB * NB * NB);

    long base = (long)n * DIM * DIM * DIM
              + (long)(bz * 16) * DIM * DIM
              + (long)(bx * 16) * DIM
              + (long)(by * 16);

    int x = t >> 4;
    int y = t & 15;
    // the x-neighbor NOT covered by shfl_xor16: even x -> x-1, odd x -> x+1
    bool xv = (x & 1) ? (x < 15) : (x > 0);
    int to = xv ? ((x & 1) ? t + 16 : t - 16) : t;   // clamped to safe self-index

    // ---- load into registers + dice partials; park pred in bC ----
    float g[16], p[16];
    float pg = 0.f, pp = 0.f, gg = 0.f;
#pragma unroll
    for (int k = 0; k < 16; k++) {
        long gi = base + (long)k * DIM * DIM + x * DIM + y;
        float gv = gt[gi];
        float pv = pred[gi];
        g[k] = gv;
        p[k] = pv;
        bC[(k << 8) + t] = pv;
        pg += pv * gv;
        pp += pv * pv;
        gg += gv * gv;
    }

    // NOTE: reference's boundary conv kernel is -(ones.at[13].set(26)) -- all taps
    // negative -- so (b > 0.1) is identically false and loss_bdr == 0. Term dropped.

    float skel_g[16], skel_p[16];
    soft_skel_reg(bA, bB, g, skel_g, t, to, xv, y);   // gt skel (destroys g)

#pragma unroll
    for (int k = 0; k < 16; k++) p[k] = bC[(k << 8) + t];   // own column, no sync needed

    soft_skel_reg(bA, bB, p, skel_p, t, to, xv, y);   // pred skel

    // ---- clDice tversky counts (registers only) ----
    float tpc = 0.f, fnc = 0.f, fpc = 0.f;
#pragma unroll
    for (int k = 0; k < 16; k++) {
        float sg = skel_g[k];
        float sp = skel_p[k];
        tpc += sg * sp;
        fnc += sg * (1.0f - sp);
        fpc += (1.0f - sg) * sp;
    }

    // ---- block reduction ----
    __shared__ float red[8][6];
    float vals[6] = {pg, pp, gg, tpc, fnc, fpc};
    int lane = t & 31, w = t >> 5;
#pragma unroll
    for (int i = 0; i < 6; i++) {
        float s = warp_sum(vals[i]);
        if (lane == 0) red[w][i] = s;
    }
    __syncthreads();

    if (t == 0) {
        double s[6];
#pragma unroll
        for (int i = 0; i < 6; i++) {
            double acc = 0.0;
#pragma unroll
            for (int ww = 0; ww < 8; ww++) acc += (double)red[ww][i];
            s[i] = acc;
        }
        atomicAdd(&g_acc[0], s[0]);
        atomicAdd(&g_acc[1], s[1]);
        atomicAdd(&g_acc[2], s[2]);
        atomicAdd(&g_acc[3], block_tversky(s[3], s[4], s[5]));
    }
}

__global__ void final_kernel(const float* __restrict__ w1,
                             const float* __restrict__ w2,
                             float* __restrict__ out, int M) {
    double pg = g_acc[0], pp = g_acc[1], gg = g_acc[2];
    double dice = 2.0 * pg / fmax(pp + gg, 1e-6);
    double dice_loss = 1.0 - dice;
    double w1s = (double)w1[0], w2s = (double)w2[0];
    double edge = (g_acc[3] / (w2s * w2s)) / (2.0 * (double)M)
                + log(1.0 + fabs(w1s) * fabs(w2s));
    out[0] = (float)((dice < 0.8) ? dice_loss : dice_loss + edge);
}

extern "C" void kernel_launch(void* const* d_in, const int* in_sizes, int n_in,
                              void* d_out, int out_size) {
    const float* pred = (const float*)d_in[0];
    const float* gt   = (const float*)d_in[1];
    const float* w1   = (const float*)d_in[2];
    const float* w2   = (const float*)d_in[3];
    float* out = (float*)d_out;

    int total = in_sizes[0];
    int N = total / (DIM * DIM * DIM);
    int nblk = N * NB * NB * NB;

    cudaFuncSetAttribute(loss_main_kernel,
                         cudaFuncAttributeMaxDynamicSharedMemorySize,
                         3 * BLKV * (int)sizeof(float));

    init_acc_kernel<<<1, 32>>>();
    loss_main_kernel<<<nblk, THREADS, 3 * BLKV * sizeof(float)>>>(pred, gt);
    final_kernel<<<1, 1>>>(w1, w2, out, nblk);
}

// round 10
// speedup vs baseline: 11.6507x; 1.0745x over previous
#include <cuda_runtime.h>
#include <math.h>

#define DIM 192
#define NB 12
#define BLKV 4096
#define THREADS 256
#define FULLM 0xffffffffu
#define NEG_INF (-3.402823466e+38f)

// accumulators: [0]=sum(p*g) [1]=sum(p*p) [2]=sum(g*g) [3]=loss_cl
__device__ double g_acc[4];

__global__ void init_acc_kernel() {
    if (threadIdx.x < 4) g_acc[threadIdx.x] = 0.0;
}

__device__ __forceinline__ float warp_sum(float v) {
#pragma unroll
    for (int o = 16; o; o >>= 1) v += __shfl_xor_sync(FULLM, v, o);
    return v;
}

// ---------------------------------------------------------------------------
// Thread (x,y) owns a 16-z register column. lane = (x&1)*16 + y:
//   y+-1 : lane+-1 shfl (y-guards keep it inside the 16-lane half)
//   x^1  : lane^16 shfl (always a valid x neighbor)
//   other x : smem (published buffer), 1 guarded LDS
// Pipeline: each erosion level e_i is published ONCE; both dilate(e_i) and
// erode(e_i)->e_{i+1} consume that buffer. One __syncthreads per publish.
// Buffers A/B strictly alternate.
// ---------------------------------------------------------------------------

__device__ __forceinline__ void publish(const float (&v)[16], float* __restrict__ buf, int t) {
#pragma unroll
    for (int k = 0; k < 16; k++) buf[(k << 8) + t] = v[k];
    __syncthreads();
}

// e = erode(v): min over z+-1 (regs), x (shfl + smem), y (shfl). +inf pad.
__device__ __forceinline__ void erode_c(const float (&v)[16], float (&e)[16],
                                        const float* __restrict__ buf,
                                        int to, bool xv, int y) {
#pragma unroll
    for (int k = 0; k < 16; k++) {
        float m = v[k];
        if (k > 0)   m = fminf(m, v[k - 1]);
        if (k < 15)  m = fminf(m, v[k + 1]);
        m = fminf(m, __shfl_xor_sync(FULLM, v[k], 16));
        float o = buf[(k << 8) + to];
        if (xv) m = fminf(m, o);
        float yu = __shfl_up_sync(FULLM, v[k], 1);
        if (y > 0)  m = fminf(m, yu);
        float yd = __shfl_down_sync(FULLM, v[k], 1);
        if (y < 15) m = fminf(m, yd);
        e[k] = m;
    }
}

// dilate(e) (3x3x3 max, -inf pad) fused with skel init/update.
// z-max of own column from regs; xor-partner column via rolling shfl window;
// other-x column via rolling LDS window; y-pass via shfl. No publish, no sync.
template <bool FIRST>
__device__ __forceinline__ void dilate_c(const float (&e)[16], const float (&prev)[16],
                                         float (&skel)[16],
                                         const float* __restrict__ buf,
                                         int to, bool xv, int y) {
    // rolling windows: values at k-1, k, k+1 for xor-partner and other-x columns
    float xr0 = __shfl_xor_sync(FULLM, e[0], 16);
    float xo0 = buf[to];
    float xr_m1 = NEG_INF, xo_m1 = NEG_INF;
#pragma unroll
    for (int k = 0; k < 16; k++) {
        float xr_p1 = (k < 15) ? __shfl_xor_sync(FULLM, e[k + 1], 16) : NEG_INF;
        float xo_p1 = (k < 15) ? buf[((k + 1) << 8) + to] : NEG_INF;
        // own z-max
        float m = e[k];
        if (k > 0)   m = fmaxf(m, e[k - 1]);
        if (k < 15)  m = fmaxf(m, e[k + 1]);
        // xor-partner z-max (always valid x neighbor)
        m = fmaxf(m, fmaxf(xr0, fmaxf(xr_m1, xr_p1)));
        // other-x z-max (guarded)
        float zo = fmaxf(xo0, fmaxf(xo_m1, xo_p1));
        if (xv) m = fmaxf(m, zo);
        // y-pass on the completed xz-max
        float yu = __shfl_up_sync(FULLM, m, 1);
        float yd = __shfl_down_sync(FULLM, m, 1);
        float d = m;
        if (y > 0)  d = fmaxf(d, yu);
        if (y < 15) d = fmaxf(d, yd);
        // skel update
        float delta = fmaxf(prev[k] - d, 0.0f);
        if (FIRST) {
            skel[k] = delta;
        } else {
            float s = skel[k];
            skel[k] = s + fmaxf(delta - s * delta, 0.0f);
        }
        xr_m1 = xr0; xr0 = xr_p1;
        xo_m1 = xo0; xo0 = xo_p1;
    }
}

// soft_skel ITERS=3. img destroyed (reused for e-levels). 5 publishes/syncs.
// Buffer alternation: caller passes the buffer to use FIRST; strict A/B after.
__device__ __forceinline__ void soft_skel2(float (&img)[16], float (&skel)[16],
                                           float* __restrict__ b0, float* __restrict__ b1,
                                           int t, int to, bool xv, int y) {
    float e1[16], e2[16];

    publish(img, b0, t);
    erode_c(img, e1, b0, to, xv, y);            // e1 = erode(img)
    publish(e1, b1, t);
    dilate_c<true>(e1, img, skel, b1, to, xv, y);   // skel = relu(img - dil(e1)); img dead
    erode_c(e1, e2, b1, to, xv, y);             // e2
    publish(e2, b0, t);
    dilate_c<false>(e2, e1, skel, b0, to, xv, y);   // delta vs e1
    erode_c(e2, img, b0, to, xv, y);            // img <- e3
    publish(img, b1, t);
    dilate_c<false>(img, e2, skel, b1, to, xv, y);  // delta vs e2
    erode_c(img, e1, b1, to, xv, y);            // e1 <- e4
    publish(e1, b0, t);
    dilate_c<false>(e1, img, skel, b0, to, xv, y);  // delta vs e3
}

__device__ __forceinline__ double block_tversky(double tp, double fn, double fp) {
    const double s = 1e-8;
    double ab = fp + fn + s;
    double alpha = 0.5 + 0.5 * (fp + s) / ab;
    double beta  = 0.5 + 0.5 * (fn + s) / ab;
    return 1.0 - (tp + s) / (tp + alpha * fp + beta * fn + s);
}

extern __shared__ float smem[];

__global__ void __launch_bounds__(THREADS, 3)
loss_main_kernel(const float* __restrict__ pred, const float* __restrict__ gt) {
    float* bA = smem;              // exchange buffer A
    float* bB = smem + BLKV;       // exchange buffer B
    float* bC = smem + 2 * BLKV;   // skel_g stash
    __shared__ float red[8][6];

    int t = threadIdx.x;
    int b = blockIdx.x;
    int by = b % NB;
    int bx = (b / NB) % NB;
    int bz = (b / (NB * NB)) % NB;
    int n  = b / (NB * NB * NB);

    long base = (long)n * DIM * DIM * DIM
              + (long)(bz * 16) * DIM * DIM
              + (long)(bx * 16) * DIM
              + (long)(by * 16);

    int x = t >> 4;
    int y = t & 15;
    bool xv = (x & 1) ? (x < 15) : (x > 0);           // other-x validity
    int to = xv ? ((x & 1) ? t + 16 : t - 16) : t;    // other-x index (safe self if !xv)
    int lane = t & 31, w = t >> 5;

    // ---- load + dice partials (banked to smem immediately to free regs) ----
    float g[16];
    {
        float pg = 0.f, pp = 0.f, gg = 0.f;
#pragma unroll
        for (int k = 0; k < 16; k++) {
            long gi = base + (long)k * DIM * DIM + x * DIM + y;
            float gv = gt[gi];
            float pv = pred[gi];
            g[k] = gv;
            pg += pv * gv;
            pp += pv * pv;
            gg += gv * gv;
        }
        float s0 = warp_sum(pg), s1 = warp_sum(pp), s2 = warp_sum(gg);
        if (lane == 0) { red[w][0] = s0; red[w][1] = s1; red[w][2] = s2; }
    }

    // NOTE: reference's boundary conv kernel is -(ones.at[13].set(26)) -- all taps
    // negative -- so (b > 0.1) is identically false and loss_bdr == 0. Term dropped.

    float skel_g[16], skel_p[16];
    soft_skel2(g, skel_g, bA, bB, t, to, xv, y);   // gt skel; last publish hit bA... (b0 start A)

    // stash gt skel (own column, no sync needed for self-access)
#pragma unroll
    for (int k = 0; k < 16; k++) bC[(k << 8) + t] = skel_g[k];

    // reload pred from global (L2-resident: pred+gt = 57MB < 126MB L2)
    float p[16];
#pragma unroll
    for (int k = 0; k < 16; k++)
        p[k] = pred[base + (long)k * DIM * DIM + x * DIM + y];

    // second skel starts publishing into bB: bA's last readers (dilate4 of gt)
    // are ordered by the publish-sync inside soft_skel2's first publish.
    soft_skel2(p, skel_p, bB, bA, t, to, xv, y);

    // ---- clDice tversky counts ----
    float tpc = 0.f, fnc = 0.f, fpc = 0.f;
#pragma unroll
    for (int k = 0; k < 16; k++) {
        float sg = bC[(k << 8) + t];
        float sp = skel_p[k];
        tpc += sg * sp;
        fnc += sg * (1.0f - sp);
        fpc += (1.0f - sg) * sp;
    }

    {
        float s3 = warp_sum(tpc), s4 = warp_sum(fnc), s5 = warp_sum(fpc);
        if (lane == 0) { red[w][3] = s3; red[w][4] = s4; red[w][5] = s5; }
    }
    __syncthreads();

    if (t == 0) {
        double s[6];
#pragma unroll
        for (int i = 0; i < 6; i++) {
            double acc = 0.0;
#pragma unroll
            for (int ww = 0; ww < 8; ww++) acc += (double)red[ww][i];
            s[i] = acc;
        }
        atomicAdd(&g_acc[0], s[0]);
        atomicAdd(&g_acc[1], s[1]);
        atomicAdd(&g_acc[2], s[2]);
        atomicAdd(&g_acc[3], block_tversky(s[3], s[4], s[5]));
    }
}

__global__ void final_kernel(const float* __restrict__ w1,
                             const float* __restrict__ w2,
                             float* __restrict__ out, int M) {
    double pg = g_acc[0], pp = g_acc[1], gg = g_acc[2];
    double dice = 2.0 * pg / fmax(pp + gg, 1e-6);
    double dice_loss = 1.0 - dice;
    double w1s = (double)w1[0], w2s = (double)w2[0];
    double edge = (g_acc[3] / (w2s * w2s)) / (2.0 * (double)M)
                + log(1.0 + fabs(w1s) * fabs(w2s));
    out[0] = (float)((dice < 0.8) ? dice_loss : dice_loss + edge);
}

extern "C" void kernel_launch(void* const* d_in, const int* in_sizes, int n_in,
                              void* d_out, int out_size) {
    const float* pred = (const float*)d_in[0];
    const float* gt   = (const float*)d_in[1];
    const float* w1   = (const float*)d_in[2];
    const float* w2   = (const float*)d_in[3];
    float* out = (float*)d_out;

    int total = in_sizes[0];
    int N = total / (DIM * DIM * DIM);
    int nblk = N * NB * NB * NB;

    cudaFuncSetAttribute(loss_main_kernel,
                         cudaFuncAttributeMaxDynamicSharedMemorySize,
                         3 * BLKV * (int)sizeof(float));

    init_acc_kernel<<<1, 32>>>();
    loss_main_kernel<<<nblk, THREADS, 3 * BLKV * sizeof(float)>>>(pred, gt);
    final_kernel<<<1, 1>>>(w1, w2, out, nblk);
}

// round 11
// speedup vs baseline: 17.5945x; 1.5102x over previous
#include <cuda_runtime.h>
#include <math.h>

#define DIM 192
#define NB 12
#define BLKV 4096
#define THREADS 256
#define FULLM 0xffffffffu
#define NEG_INF (-3.402823466e+38f)

// accumulators: [0]=sum(p*g) [1]=sum(p*p) [2]=sum(g*g) [3]=loss_cl
__device__ double g_acc[4];

__global__ void init_acc_kernel() {
    if (threadIdx.x < 4) g_acc[threadIdx.x] = 0.0;
}

__device__ __forceinline__ float warp_sum(float v) {
#pragma unroll
    for (int o = 16; o; o >>= 1) v += __shfl_xor_sync(FULLM, v, o);
    return v;
}

// ---------------------------------------------------------------------------
// Thread (x,y) owns the 16-voxel z-column.  lane = (x&1)*16 + y:
//   y+-1 : lane+-1 shfl     x^1 : lane^16 shfl (always valid)
//   other x : smem publish + 1 LDS (guarded by xv)
//
// GT PATH (binary data): the whole column is a 16-bit mask in one register.
//   erode  = AND of 7-cross   (pads = 1)
//   dilate = OR  of 3x3x3 box (pads = 0)
//   delta  = e & ~d ;  skel |= delta
// PRED PATH (continuous): f32 register column, separable dilate, fused update.
// ---------------------------------------------------------------------------

// ============================ pred (f32) path ==============================

__device__ __forceinline__ void publish(const float (&v)[16], float* __restrict__ buf, int t) {
#pragma unroll
    for (int k = 0; k < 16; k++) buf[(k << 8) + t] = v[k];
    __syncthreads();
}

__device__ __forceinline__ void erode_c(const float (&v)[16], float (&e)[16],
                                        const float* __restrict__ buf,
                                        int to, bool xv, int y) {
#pragma unroll
    for (int k = 0; k < 16; k++) {
        float m = v[k];
        if (k > 0)   m = fminf(m, v[k - 1]);
        if (k < 15)  m = fminf(m, v[k + 1]);
        m = fminf(m, __shfl_xor_sync(FULLM, v[k], 16));
        float o = buf[(k << 8) + to];
        if (xv) m = fminf(m, o);
        float yu = __shfl_up_sync(FULLM, v[k], 1);
        if (y > 0)  m = fminf(m, yu);
        float yd = __shfl_down_sync(FULLM, v[k], 1);
        if (y < 15) m = fminf(m, yd);
        e[k] = m;
    }
}

template <bool FIRST>
__device__ __forceinline__ void dilate_c(const float (&e)[16], const float (&prev)[16],
                                         float (&skel)[16],
                                         const float* __restrict__ buf,
                                         int to, bool xv, int y) {
    float xr0 = __shfl_xor_sync(FULLM, e[0], 16);
    float xo0 = buf[to];
    float xr_m1 = NEG_INF, xo_m1 = NEG_INF;
#pragma unroll
    for (int k = 0; k < 16; k++) {
        float xr_p1 = (k < 15) ? __shfl_xor_sync(FULLM, e[k + 1], 16) : NEG_INF;
        float xo_p1 = (k < 15) ? buf[((k + 1) << 8) + to] : NEG_INF;
        float m = e[k];
        if (k > 0)   m = fmaxf(m, e[k - 1]);
        if (k < 15)  m = fmaxf(m, e[k + 1]);
        m = fmaxf(m, fmaxf(xr0, fmaxf(xr_m1, xr_p1)));
        float zo = fmaxf(xo0, fmaxf(xo_m1, xo_p1));
        if (xv) m = fmaxf(m, zo);
        float yu = __shfl_up_sync(FULLM, m, 1);
        float yd = __shfl_down_sync(FULLM, m, 1);
        float d = m;
        if (y > 0)  d = fmaxf(d, yu);
        if (y < 15) d = fmaxf(d, yd);
        float delta = fmaxf(prev[k] - d, 0.0f);
        if (FIRST) {
            skel[k] = delta;
        } else {
            float s = skel[k];
            skel[k] = s + fmaxf(delta - s * delta, 0.0f);
        }
        xr_m1 = xr0; xr0 = xr_p1;
        xo_m1 = xo0; xo0 = xo_p1;
    }
}

__device__ __forceinline__ void soft_skel_f32(float (&img)[16], float (&skel)[16],
                                              float* __restrict__ b0, float* __restrict__ b1,
                                              int t, int to, bool xv, int y) {
    float e1[16], e2[16];
    publish(img, b0, t);
    erode_c(img, e1, b0, to, xv, y);
    publish(e1, b1, t);
    dilate_c<true>(e1, img, skel, b1, to, xv, y);
    erode_c(e1, e2, b1, to, xv, y);
    publish(e2, b0, t);
    dilate_c<false>(e2, e1, skel, b0, to, xv, y);
    erode_c(e2, img, b0, to, xv, y);
    publish(img, b1, t);
    dilate_c<false>(img, e2, skel, b1, to, xv, y);
    erode_c(img, e1, b1, to, xv, y);
    publish(e1, b0, t);
    dilate_c<false>(e1, img, skel, b0, to, xv, y);
}

// ============================ gt (boolean) path ============================

// erode of 7-cross on 16-bit column mask. pads = 1 (+inf).
__device__ __forceinline__ unsigned erode_bits(unsigned cur, unsigned* __restrict__ ib,
                                               int t, int to, bool xv, int y) {
    ib[t] = cur;
    __syncthreads();
    unsigned m = cur & ((cur << 1) | 1u) & ((cur >> 1) | 0x8000u);
    m &= __shfl_xor_sync(FULLM, cur, 16);
    unsigned ox = ib[to];
    if (xv) m &= ox;
    unsigned yu = __shfl_up_sync(FULLM, cur, 1);
    if (y > 0)  m &= yu;
    unsigned yd = __shfl_down_sync(FULLM, cur, 1);
    if (y < 15) m &= yd;
    return m & 0xFFFFu;
}

// dilate 3x3x3 box (OR), pads = 0 (-inf). separable: z, then x, then y.
__device__ __forceinline__ unsigned dilate_bits(unsigned e, unsigned* __restrict__ ib,
                                                int t, int to, bool xv, int y) {
    unsigned dz = e | (e << 1) | (e >> 1);
    ib[t] = dz;
    __syncthreads();
    unsigned dx = dz | __shfl_xor_sync(FULLM, dz, 16);
    unsigned ox = ib[to];
    if (xv) dx |= ox;
    unsigned d = dx;
    unsigned yu = __shfl_up_sync(FULLM, dx, 1);
    if (y > 0)  d |= yu;
    unsigned yd = __shfl_down_sync(FULLM, dx, 1);
    if (y < 15) d |= yd;
    return d & 0xFFFFu;
}

__device__ __forceinline__ unsigned soft_skel_bits(unsigned gmask,
                                                   unsigned* __restrict__ ibA,
                                                   unsigned* __restrict__ ibB,
                                                   int t, int to, bool xv, int y) {
    unsigned cur = gmask, skel = 0;
#pragma unroll
    for (int it = 0; it < 4; it++) {
        unsigned e = erode_bits(cur, ibA, t, to, xv, y);
        unsigned d = dilate_bits(e, ibB, t, to, xv, y);
        skel |= cur & ~d;     // delta = relu(cur - dilate(erode(cur))) on binary data
        cur = e;
    }
    return skel;
}

// ===========================================================================

__device__ __forceinline__ double block_tversky(double tp, double fn, double fp) {
    const double s = 1e-8;
    double ab = fp + fn + s;
    double alpha = 0.5 + 0.5 * (fp + s) / ab;
    double beta  = 0.5 + 0.5 * (fn + s) / ab;
    return 1.0 - (tp + s) / (tp + alpha * fp + beta * fn + s);
}

extern __shared__ float smem[];

__global__ void __launch_bounds__(THREADS, 3)
loss_main_kernel(const float* __restrict__ pred, const float* __restrict__ gt) {
    float* bA = smem;              // f32 exchange A
    float* bB = smem + BLKV;       // f32 exchange B
    unsigned* ibA = (unsigned*)(smem + 2 * BLKV);          // int exchange A (256 words)
    unsigned* ibB = (unsigned*)(smem + 2 * BLKV) + 256;    // int exchange B
    __shared__ float red[8][6];

    int t = threadIdx.x;
    int b = blockIdx.x;
    int by = b % NB;
    int bx = (b / NB) % NB;
    int bz = (b / (NB * NB)) % NB;
    int n  = b / (NB * NB * NB);

    long base = (long)n * DIM * DIM * DIM
              + (long)(bz * 16) * DIM * DIM
              + (long)(bx * 16) * DIM
              + (long)(by * 16);

    int x = t >> 4;
    int y = t & 15;
    bool xv = (x & 1) ? (x < 15) : (x > 0);
    int to = xv ? ((x & 1) ? t + 16 : t - 16) : t;
    int lane = t & 31, w = t >> 5;

    // ---- load: gt packed to bits, pred to f32 regs; dice partials ----
    float p[16];
    unsigned gmask = 0;
    {
        float pg = 0.f, pp = 0.f;
#pragma unroll
        for (int k = 0; k < 16; k++) {
            long gi = base + (long)k * DIM * DIM + x * DIM + y;
            float gv = gt[gi];
            float pv = pred[gi];
            p[k] = pv;
            if (gv != 0.0f) { gmask |= (1u << k); pg += pv; }
            pp += pv * pv;
        }
        float gg = (float)__popc(gmask);   // sum g^2 == count of ones
        float s0 = warp_sum(pg), s1 = warp_sum(pp), s2 = warp_sum(gg);
        if (lane == 0) { red[w][0] = s0; red[w][1] = s1; red[w][2] = s2; }
    }

    // NOTE: reference's boundary conv kernel is -(ones.at[13].set(26)) -- all taps
    // negative -- so (b > 0.1) is identically false and loss_bdr == 0. Term dropped.

    // ---- gt skeleton: pure bitwise (binary field) ----
    unsigned skelg = soft_skel_bits(gmask, ibA, ibB, t, to, xv, y);

    // ---- pred skeleton: f32 path ----
    float skel_p[16];
    soft_skel_f32(p, skel_p, bA, bB, t, to, xv, y);

    // ---- clDice tversky counts ----
    float tpc = 0.f, fnc = 0.f, fpc = 0.f;
#pragma unroll
    for (int k = 0; k < 16; k++) {
        float sp = skel_p[k];
        if ((skelg >> k) & 1u) {
            tpc += sp;
            fnc += 1.0f - sp;
        } else {
            fpc += sp;
        }
    }

    {
        float s3 = warp_sum(tpc), s4 = warp_sum(fnc), s5 = warp_sum(fpc);
        if (lane == 0) { red[w][3] = s3; red[w][4] = s4; red[w][5] = s5; }
    }
    __syncthreads();

    if (t == 0) {
        double s[6];
#pragma unroll
        for (int i = 0; i < 6; i++) {
            double acc = 0.0;
#pragma unroll
            for (int ww = 0; ww < 8; ww++) acc += (double)red[ww][i];
            s[i] = acc;
        }
        atomicAdd(&g_acc[0], s[0]);
        atomicAdd(&g_acc[1], s[1]);
        atomicAdd(&g_acc[2], s[2]);
        atomicAdd(&g_acc[3], block_tversky(s[3], s[4], s[5]));
    }
}

__global__ void final_kernel(const float* __restrict__ w1,
                             const float* __restrict__ w2,
                             float* __restrict__ out, int M) {
    double pg = g_acc[0], pp = g_acc[1], gg = g_acc[2];
    double dice = 2.0 * pg / fmax(pp + gg, 1e-6);
    double dice_loss = 1.0 - dice;
    double w1s = (double)w1[0], w2s = (double)w2[0];
    double edge = (g_acc[3] / (w2s * w2s)) / (2.0 * (double)M)
                + log(1.0 + fabs(w1s) * fabs(w2s));
    out[0] = (float)((dice < 0.8) ? dice_loss : dice_loss + edge);
}

extern "C" void kernel_launch(void* const* d_in, const int* in_sizes, int n_in,
                              void* d_out, int out_size) {
    const float* pred = (const float*)d_in[0];
    const float* gt   = (const float*)d_in[1];
    const float* w1   = (const float*)d_in[2];
    const float* w2   = (const float*)d_in[3];
    float* out = (float*)d_out;

    int total = in_sizes[0];
    int N = total / (DIM * DIM * DIM);
    int nblk = N * NB * NB * NB;

    int smem_bytes = 2 * BLKV * (int)sizeof(float) + 512 * (int)sizeof(unsigned);
    cudaFuncSetAttribute(loss_main_kernel,
                         cudaFuncAttributeMaxDynamicSharedMemorySize, smem_bytes);

    init_acc_kernel<<<1, 32>>>();
    loss_main_kernel<<<nblk, THREADS, smem_bytes>>>(pred, gt);
    final_kernel<<<1, 1>>>(w1, w2, out, nblk);
}